// round 17
// baseline (speedup 1.0000x reference)
#include <cuda_runtime.h>
#include <cuda_bf16.h>
#include <cuda_fp16.h>
#include <cstdint>

// BiATT algebraic collapse: softmax over axis=1 of a [N,1] tensor == 1.0, so
// all four bi-attention branches are identity. cf = atoms @ (sum Wcc blocks) + bcc,
// pf = amino @ (sum Wcp blocks) + bcp  =>  two [6144x512]@[512x512] GEMMs.
// Single fp16 GEMM (fp32 accum), rel_err 2.93e-4 (stable since R7).
// R17: warp-specialized producer (warp 8 of 9) — all TMA issues serialized in
// ONE thread's program order (race-free like R15), but that thread never
// computes, so empty-waits cannot delay MMA issue (kills the convoy R16's
// racy rotation tried to fix). Warps 0-7: 64x32 tiles, unchanged.

#define DIM     512
#define M_ROWS  6144
#define BM      128
#define BN      128
#define BK      64
#define NCHUNK  (DIM / BK)     // 8 per tile
#define NTILES  384            // 4 nblk x 48 mblk x 2 z
#define NPERS   296            // persistent CTAs = 148 SMs x occ 2
#define BLKB    16384          // 16KB block: 128 rows x 64 fp16, swizzled
#define NCONS   8              // consumer warps

// tile-blocked, pre-swizzled fp16 operands (uint4 => 16B-aligned for bulk copy)
__device__ uint4 g_A4[2 * 48 * 8 * (BLKB / 16)];   // [z][mtile][chunk][16KB]
__device__ uint4 g_W4[2 * 4 * 8 * (BLKB / 16)];    // [z][ntile][chunk][16KB]

// ---- smem: 3 stages x (A 16KB + B 16KB); 6 mbarriers
#define SM_A      0
#define SM_B      16384
#define SM_STAGE  32768
#define SM_MBAR   (3 * SM_STAGE)        // 98304: full[3] then empty[3]
#define SM_TOT    (SM_MBAR + 64)        // 98368 dynamic (occ 2)

// ---------------------------------------------------------------- helpers
__device__ __forceinline__ uint32_t smem_u32(const void* p) {
    return (uint32_t)__cvta_generic_to_shared(p);
}
__device__ __forceinline__ uint32_t sw128(uint32_t off) {
    return off ^ ((off >> 3) & 0x70);
}
__device__ __forceinline__ void bulk_cp(uint32_t dst, const void* src,
                                        uint32_t bytes, uint32_t mbar) {
    asm volatile(
        "cp.async.bulk.shared::cluster.global.mbarrier::complete_tx::bytes "
        "[%0], [%1], %2, [%3];"
        :: "r"(dst), "l"(src), "r"(bytes), "r"(mbar) : "memory");
}
__device__ __forceinline__ void mbar_init(uint32_t mbar, uint32_t cnt) {
    asm volatile("mbarrier.init.shared.b64 [%0], %1;" :: "r"(mbar), "r"(cnt)
                 : "memory");
}
__device__ __forceinline__ void mbar_expect(uint32_t mbar, uint32_t tx) {
    asm volatile("mbarrier.arrive.expect_tx.shared.b64 _, [%0], %1;"
                 :: "r"(mbar), "r"(tx) : "memory");
}
__device__ __forceinline__ void mbar_arrive(uint32_t mbar) {
    asm volatile("mbarrier.arrive.shared.b64 _, [%0];" :: "r"(mbar) : "memory");
}
__device__ __forceinline__ void mbar_wait(uint32_t mbar, uint32_t parity) {
    asm volatile(
        "{\n\t.reg .pred P1;\n\t"
        "WAIT_LOOP_%=:\n\t"
        "mbarrier.try_wait.parity.acquire.cta.shared::cta.b64 P1, [%0], %1, 0x989680;\n\t"
        "@P1 bra.uni WAIT_DONE_%=;\n\t"
        "bra.uni WAIT_LOOP_%=;\n\t"
        "WAIT_DONE_%=:\n\t}"
        :: "r"(mbar), "r"(parity) : "memory");
}
__device__ __forceinline__ void ldsm_x4(uint32_t* r, uint32_t addr) {
    asm volatile("ldmatrix.sync.aligned.m8n8.x4.shared.b16 {%0,%1,%2,%3}, [%4];"
                 : "=r"(r[0]), "=r"(r[1]), "=r"(r[2]), "=r"(r[3]) : "r"(addr));
}
__device__ __forceinline__ void mma_f16(float* d, const uint32_t* a,
                                        uint32_t b0, uint32_t b1) {
    asm volatile(
        "mma.sync.aligned.m16n8k16.row.col.f32.f16.f16.f32 "
        "{%0,%1,%2,%3}, {%4,%5,%6,%7}, {%8,%9}, {%0,%1,%2,%3};"
        : "+f"(d[0]), "+f"(d[1]), "+f"(d[2]), "+f"(d[3])
        : "r"(a[0]), "r"(a[1]), "r"(a[2]), "r"(a[3]), "r"(b0), "r"(b1));
}

// ---------------------------- fused prologue: fold-W + convert-A, blocked+swizzled
// grid (256 + 384, 2):  x<256 fold-W,  x>=256 convert-A  (unchanged from R12)
__global__ void __launch_bounds__(256)
prep_kernel(const float* __restrict__ atoms, const float* __restrict__ amino,
            const float* __restrict__ Wcc,   const float* __restrict__ Wcp) {
    const int z   = blockIdx.y;
    const int tid = threadIdx.x;
    char* gA = reinterpret_cast<char*>(g_A4);
    char* gW = reinterpret_cast<char*>(g_W4);

    if (blockIdx.x < 256) {
        __shared__ float s[32][33];
        const float* __restrict__ W = z ? Wcp : Wcc;
        const int nb = blockIdx.x & 15;
        const int kb = blockIdx.x >> 4;
        const int n0 = nb * 32;
        const int k0 = kb * 32;
        const int tx = tid & 31;
        const int ty = tid >> 5;
        float v[4] = {0.f, 0.f, 0.f, 0.f};
#pragma unroll
        for (int b = 0; b < 4; b++) {
#pragma unroll
            for (int i = 0; i < 4; i++) {
                const int k = k0 + ty + i * 8;
                v[i] += W[(size_t)(b * DIM + k) * DIM + n0 + tx];
            }
        }
#pragma unroll
        for (int i = 0; i < 4; i++) s[tx][ty + i * 8] = v[i];
        __syncthreads();
#pragma unroll
        for (int i = 0; i < 4; i++) {
            const int n2 = n0 + ty + i * 8;
            const int k2 = k0 + tx;
            const int ntile = n2 >> 7;
            const int c     = k2 >> 6;
            const size_t base = (size_t)(((z * 4 + ntile) * 8 + c)) * BLKB;
            const uint32_t off = sw128((uint32_t)((n2 & 127) * 128 + (k2 & 63) * 2));
            *reinterpret_cast<__half*>(gW + base + off) =
                __float2half_rn(s[ty + i * 8][tx]);
        }
    } else {
        const float* __restrict__ X = z ? amino : atoms;
        const int cb = blockIdx.x - 256;
        const int m  = cb >> 3;
        const int c  = cb & 7;
        float4 v[8];
        int   rows[8], cols[8];
#pragma unroll
        for (int it = 0; it < 8; it++) {
            const int gidx = it * 1024 + tid * 4;
            rows[it] = gidx >> 6;
            cols[it] = gidx & 63;
            v[it] = *reinterpret_cast<const float4*>(
                &X[(size_t)(m * 128 + rows[it]) * DIM + c * 64 + cols[it]]);
        }
        char* dst = gA + (size_t)((z * 48 + m) * 8 + c) * BLKB;
#pragma unroll
        for (int it = 0; it < 8; it++) {
            __half2 h0 = __floats2half2_rn(v[it].x, v[it].y);
            __half2 h1 = __floats2half2_rn(v[it].z, v[it].w);
            uint2 o = make_uint2(*reinterpret_cast<uint32_t*>(&h0),
                                 *reinterpret_cast<uint32_t*>(&h1));
            const uint32_t off =
                sw128((uint32_t)(rows[it] * 128 + cols[it] * 2));
            *reinterpret_cast<uint2*>(dst + off) = o;
        }
    }
}

// --------------------------------------------------- persistent HMMA GEMM
// grid 296, 288 threads: warps 0-7 consume (64x32 tiles), warp 8 produces
__global__ void __launch_bounds__(288, 2)
biatt_gemm_kernel(const float* __restrict__ bcc,
                  const float* __restrict__ bcp,
                  float* __restrict__ out) {
    extern __shared__ __align__(16) char sm[];
    const uint32_t sbase = smem_u32(sm);

    const int tid  = threadIdx.x;
    const int wid  = tid >> 5;
    const int lane = tid & 31;
    const char* gA = reinterpret_cast<const char*>(g_A4);
    const char* gW = reinterpret_cast<const char*>(g_W4);

    const uint32_t fullB  = sbase + SM_MBAR;        // full[s]  at +8s
    const uint32_t emptyB = sbase + SM_MBAR + 24;   // empty[s] at +8s

    if (tid == 0) {
#pragma unroll
        for (int s = 0; s < 3; ++s) {
            mbar_init(fullB  + s * 8, 1);
            mbar_init(emptyB + s * 8, NCONS);   // consumers only arrive
        }
    }
    __syncthreads();   // only CTA-wide barrier in the kernel

    const int ntiles  = (blockIdx.x + NPERS < NTILES) ? 2 : 1;
    const int nchunks = ntiles * NCHUNK;

    if (wid == 8) {
        // ================= producer warp: serialized TMA issue =================
        if (lane == 0) {
            for (int gg = 0; gg < nchunks; ++gg) {
                const int s2 = gg % 3;
                if (gg >= 3)   // stage reused: wait all consumers drained prior use
                    mbar_wait(emptyB + s2 * 8, (uint32_t)((gg / 3 - 1) & 1));
                const int t   = blockIdx.x + (gg >> 3) * NPERS;
                const int z   = t / 192;
                const int rem = t - z * 192;
                const int c   = gg & 7;
                const char* sA = gA + (size_t)((z * 48 + (rem >> 2)) * 8 + c) * BLKB;
                const char* sB = gW + (size_t)((z * 4  + (rem & 3))  * 8 + c) * BLKB;
                const uint32_t st = sbase + (uint32_t)(s2 * SM_STAGE);
                mbar_expect(fullB + s2 * 8, 2 * BLKB);
                bulk_cp(st + SM_A, sA, BLKB, fullB + s2 * 8);
                bulk_cp(st + SM_B, sB, BLKB, fullB + s2 * 8);
            }
        }
        return;
    }

    // ==================== consumer warps 0-7 (64x32 tiles) ====================
    const int mw = (wid >> 2) * 64;     // warp m offset (0 or 64)
    const int nw = (wid & 3) * 32;      // warp n offset (0,32,64,96)

    // ldmatrix lane constants (swizzled rows of 128B, XOR (R&7)<<4).
    const uint32_t rowA  = (uint32_t)(mw + (lane & 15)) * 128;
    const uint32_t xA    = (uint32_t)(((lane & 15) & 7) << 4);
    const uint32_t colA0 = (uint32_t)((lane >> 4) << 4);
    const uint32_t rowB  = (uint32_t)(nw + ((lane >> 4) << 3) + (lane & 7)) * 128;
    const uint32_t xB    = (uint32_t)((lane & 7) << 4);
    const uint32_t colB0 = (uint32_t)(((lane >> 3) & 1) << 4);

    float acc[4][4][4];
#pragma unroll
    for (int i = 0; i < 4; i++)
#pragma unroll
        for (int j = 0; j < 4; j++)
#pragma unroll
            for (int e = 0; e < 4; e++) acc[i][j][e] = 0.f;

    for (int g = 0; g < nchunks; ++g) {
        const int s = g % 3;

        // wait chunk g data
        mbar_wait(fullB + s * 8, (uint32_t)((g / 3) & 1));

        const uint32_t stb = sbase + (uint32_t)(s * SM_STAGE);
        const uint32_t aBase = stb + SM_A + rowA;
        const uint32_t bBase = stb + SM_B + rowB;
#pragma unroll
        for (int ks = 0; ks < 4; ++ks) {
            const uint32_t cb = (uint32_t)(ks * 32);
            const uint32_t aCol = (colA0 + cb) ^ xA;
            const uint32_t bCol = (colB0 + cb) ^ xB;
            uint32_t af[4][4];
#pragma unroll
            for (int mt = 0; mt < 4; ++mt)
                ldsm_x4(af[mt], aBase + mt * 2048 + aCol);
#pragma unroll
            for (int j2 = 0; j2 < 2; ++j2) {
                uint32_t bf[4];
                ldsm_x4(bf, bBase + j2 * 2048 + bCol);
#pragma unroll
                for (int mt = 0; mt < 4; ++mt) {
                    mma_f16(acc[mt][j2 * 2],     af[mt], bf[0], bf[1]);
                    mma_f16(acc[mt][j2 * 2 + 1], af[mt], bf[2], bf[3]);
                }
            }
        }
        if (lane == 0) mbar_arrive(emptyB + s * 8);   // stage drained (this warp)

        // ---- per-warp epilogue at tile end (overlaps other warps' compute)
        if ((g & 7) == 7) {
            const int t   = blockIdx.x + (g >> 3) * NPERS;
            const int z   = t / 192;
            const int rem = t - z * 192;
            const int n0  = (rem & 3) * BN;
            const int m0  = (rem >> 2) * BM;
            const float* __restrict__ bias = (z ? bcp : bcc) + n0;
            float* C = out + (size_t)z * M_ROWS * DIM + (size_t)m0 * DIM + n0;
#pragma unroll
            for (int mt = 0; mt < 4; ++mt) {
                const int r0 = mw + mt * 16 + (lane >> 2);
#pragma unroll
                for (int nt = 0; nt < 4; ++nt) {
                    const int cl = nw + nt * 8 + (lane & 3) * 2;
                    const float2 bv = __ldg(reinterpret_cast<const float2*>(bias + cl));
                    float2 v0 = make_float2(acc[mt][nt][0] + bv.x,
                                            acc[mt][nt][1] + bv.y);
                    float2 v1 = make_float2(acc[mt][nt][2] + bv.x,
                                            acc[mt][nt][3] + bv.y);
                    *reinterpret_cast<float2*>(&C[(size_t)r0 * DIM + cl]) = v0;
                    *reinterpret_cast<float2*>(&C[(size_t)(r0 + 8) * DIM + cl]) = v1;
                    acc[mt][nt][0] = 0.f; acc[mt][nt][1] = 0.f;
                    acc[mt][nt][2] = 0.f; acc[mt][nt][3] = 0.f;
                }
            }
        }
    }
}

// ------------------------------------------------------------------ launch
extern "C" void kernel_launch(void* const* d_in, const int* in_sizes, int n_in,
                              void* d_out, int out_size) {
    const float* atoms = (const float*)d_in[0];
    const float* amino = (const float*)d_in[1];
    const float* Wcc   = (const float*)d_in[15];
    const float* bcc   = (const float*)d_in[16];
    const float* Wcp   = (const float*)d_in[17];
    const float* bcp   = (const float*)d_in[18];
    float* out = (float*)d_out;

    static bool attr_set = false;
    if (!attr_set) {
        cudaFuncSetAttribute(biatt_gemm_kernel,
                             cudaFuncAttributeMaxDynamicSharedMemorySize, SM_TOT);
        attr_set = true;
    }

    prep_kernel<<<dim3(256 + 384, 2), 256>>>(atoms, amino, Wcc, Wcp);
    biatt_gemm_kernel<<<NPERS, 288, SM_TOT>>>(bcc, bcp, out);
}